// round 16
// baseline (speedup 1.0000x reference)
#include <cuda_runtime.h>
#include <math.h>

// ---------------------------------------------------------------------------
// Fully fused kernel: 2 images per block, ONE image per thread (warp-split).
// The circuit factorizes into wire pairs {0,1} and {2,3}: U = U_A (x) U_B, and
// each PauliZ expectation is a 9-term bilinear form over (1, cos d, sin d).
//
// Block = 448 threads (14 warps), grid = 1024:
//   warps 0-6  : image 2b   (thread t   = patch t,   t < 196)
//   warps 7-13 : image 2b+1 (thread t-224 = patch,   t-224 < 196)
// Per-thread state is halved vs the 2-img/thread variant (4 float4 x-regs,
// 4 sincos, 4 features, 10 accs) -> ~50 regs -> high occupancy, and the
// per-thread critical path is halved too.
//   - all threads issue x loads first; warp 0 does the tiny theta prep
//   - ONE __syncthreads, then conv -> sincos -> 9-term eval -> register GEMV
//     (10x LDG.128 of W, L1-hot) -> warp shfl reduce (single image per warp)
//   - warp 0 combines 7 warp-partials per image + dual log_softmax
// ---------------------------------------------------------------------------

__device__ __forceinline__ void ap1(float* vr, float* vi, int m,
    float g00r, float g00i, float g01r, float g01i,
    float g10r, float g10i, float g11r, float g11i)
{
    #pragma unroll
    for (int z = 0; z < 4; z++) {
        if (z & m) continue;
        int z1 = z | m;
        float ar = vr[z],  ai = vi[z];
        float br = vr[z1], bi = vi[z1];
        vr[z]  = g00r*ar - g00i*ai + g01r*br - g01i*bi;
        vi[z]  = g00r*ai + g00i*ar + g01r*bi + g01i*br;
        vr[z1] = g10r*ar - g10i*ai + g11r*br - g11i*bi;
        vi[z1] = g10r*ai + g10i*ar + g11r*bi + g11i*br;
    }
}

__global__ __launch_bounds__(448)
void fused_kernel(const float* __restrict__ x,
                  const float* __restrict__ cw,
                  const float* __restrict__ theta,
                  const float* __restrict__ W,
                  const float* __restrict__ bvec,
                  float* __restrict__ out)
{
    __shared__ float Ur[2][4][4], Ui[2][4][4];     // [pair][z][col]
    __shared__ float Msh[2][4][4][2];              // [pair][i][j][q]
    __shared__ float2 scA[9], scB[9];              // 9-term coeffs per pair
    __shared__ float wpart[14][10];                // [warp][k]
    __shared__ float slog[2][10];
    __shared__ float slse[2];

    int t = threadIdx.x;
    int b = blockIdx.x;                            // images 2b, 2b+1

    int wid  = t >> 5;                             // 0..13
    int lane = t & 31;
    int half = (wid >= 7) ? 1 : 0;                 // 0 = image A, 1 = image B
    int p    = half ? (t - 224) : t;               // patch index
    bool act = (p < 196);

    // ---- Step 0: issue x loads immediately ----
    float4 x0a, x0b, x1a, x1b;
    if (act) {
        int r  = p / 7;
        int c4 = p % 7;
        const float* px = x + (size_t)(2 * b + half) * 3136
                            + (size_t)(2 * r) * 56 + 8 * c4;
        x0a = *(const float4*)(px);
        x0b = *(const float4*)(px + 4);
        x1a = *(const float4*)(px + 56);
        x1b = *(const float4*)(px + 60);
    }
    float w00 = cw[0], w01 = cw[1], w10 = cw[2], w11 = cw[3];

    // ---- Prep: warp 0 only ----
    if (t < 32) {
        if (t < 8) {
            int pair = t >> 2;
            int col  = t & 3;
            float vr[4] = {0.f, 0.f, 0.f, 0.f};
            float vi[4] = {0.f, 0.f, 0.f, 0.f};
            vr[col] = 1.f;
            if (pair == 0) {
                // Ry(th0) w0, Rx(th1) w1, CNOT(0,1), Rx(th4) w0
                { float c = cosf(0.5f*theta[0]), s = sinf(0.5f*theta[0]);
                  ap1(vr, vi, 2,  c,0.f, -s,0.f,  s,0.f,  c,0.f); }
                { float c = cosf(0.5f*theta[1]), s = sinf(0.5f*theta[1]);
                  ap1(vr, vi, 1,  c,0.f, 0.f,-s, 0.f,-s,  c,0.f); }
                { float tr = vr[2], ti = vi[2];
                  vr[2] = vr[3]; vi[2] = vi[3]; vr[3] = tr; vi[3] = ti; }
                { float c = cosf(0.5f*theta[4]), s = sinf(0.5f*theta[4]);
                  ap1(vr, vi, 2,  c,0.f, 0.f,-s, 0.f,-s,  c,0.f); }
            } else {
                // Rz(th2) w2, Ry(th3) w3, CNOT(2,3), Rz(th5) w3
                { float c = cosf(0.5f*theta[2]), s = sinf(0.5f*theta[2]);
                  ap1(vr, vi, 2,  c,-s, 0.f,0.f, 0.f,0.f,  c,s); }
                { float c = cosf(0.5f*theta[3]), s = sinf(0.5f*theta[3]);
                  ap1(vr, vi, 1,  c,0.f, -s,0.f,  s,0.f,  c,0.f); }
                { float tr = vr[2], ti = vi[2];
                  vr[2] = vr[3]; vi[2] = vi[3]; vr[3] = tr; vi[3] = ti; }
                { float c = cosf(0.5f*theta[5]), s = sinf(0.5f*theta[5]);
                  ap1(vr, vi, 1,  c,-s, 0.f,0.f, 0.f,0.f,  c,s); }
            }
            #pragma unroll
            for (int z = 0; z < 4; z++) { Ur[pair][z][col] = vr[z]; Ui[pair][z][col] = vi[z]; }
        }
        __syncwarp();
        {
            int pair = t >> 4;
            int i = (t >> 2) & 3, j = t & 3;
            float p0 = 0.f, p1 = 0.f;
            #pragma unroll
            for (int z = 0; z < 4; z++) {
                float re = Ur[pair][z][i]*Ur[pair][z][j] + Ui[pair][z][i]*Ui[pair][z][j];
                p0 += (z & 2) ? -re : re;
                p1 += (z & 1) ? -re : re;
            }
            Msh[pair][i][j][0] = p0;
            Msh[pair][i][j][1] = p1;
        }
        __syncwarp();
        if (t < 18) {
            int pair = (t >= 9) ? 1 : 0;
            int e = pair ? (t - 9) : t;
            int e0 = e / 3, e1 = e % 3;
            float c0 = 0.f, c1 = 0.f;
            #pragma unroll
            for (int s = 0; s < 4; s++) {
                int i = 0, j = 0; float sg = 1.f;
                { int bsel = s & 1; int iw, jw; float ss;
                  if (e0 == 0)      { iw = bsel; jw = bsel;     ss = 1.f; }
                  else if (e0 == 1) { iw = bsel; jw = bsel;     ss = bsel ? -1.f : 1.f; }
                  else              { iw = bsel; jw = 1 - bsel; ss = 1.f; }
                  i |= iw << 1; j |= jw << 1; sg *= ss; }
                { int bsel = (s >> 1) & 1; int iw, jw; float ss;
                  if (e1 == 0)      { iw = bsel; jw = bsel;     ss = 1.f; }
                  else if (e1 == 1) { iw = bsel; jw = bsel;     ss = bsel ? -1.f : 1.f; }
                  else              { iw = bsel; jw = 1 - bsel; ss = 1.f; }
                  i |= iw; j |= jw; sg *= ss; }
                c0 += sg * Msh[pair][i][j][0];
                c1 += sg * Msh[pair][i][j][1];
            }
            float2 v = make_float2(0.25f * c0, 0.25f * c1);
            if (pair == 0) scA[e] = v; else scB[e] = v;
        }
    }

    // ---- Conv + sincos (independent of prep; before the sync) ----
    float f1a = 1.f, f2a = 0.f, f1b = 1.f, f2b = 0.f;
    float f1c = 1.f, f2c = 0.f, f1d = 1.f, f2d = 0.f;
    if (act) {
        float d0 = w00*x0a.x + w01*x0a.y + w10*x1a.x + w11*x1a.y;
        float d1 = w00*x0a.z + w01*x0a.w + w10*x1a.z + w11*x1a.w;
        float d2 = w00*x0b.x + w01*x0b.y + w10*x1b.x + w11*x1b.y;
        float d3 = w00*x0b.z + w01*x0b.w + w10*x1b.z + w11*x1b.w;
        __sincosf(d0, &f2a, &f1a);
        __sincosf(d1, &f2b, &f1b);
        __sincosf(d2, &f2c, &f1c);
        __sincosf(d3, &f2d, &f1d);
    }
    __syncthreads();   // coefficients ready

    // ---- 9-term eval -> 4 feature registers ----
    float m0 = 0.f, m1 = 0.f, m2 = 0.f, m3 = 0.f;
    if (act) {
        float fa[3] = {1.f, f1a, f2a};
        float fb[3] = {1.f, f1b, f2b};
        float fc[3] = {1.f, f1c, f2c};
        float fd[3] = {1.f, f1d, f2d};
        int idx = 0;
        #pragma unroll
        for (int e0 = 0; e0 < 3; e0++) {
            #pragma unroll
            for (int e1 = 0; e1 < 3; e1++) {
                float2 kA = scA[idx];
                float2 kB = scB[idx];
                idx++;
                float pA = fa[e0] * fb[e1];
                float pB = fc[e0] * fd[e1];
                m0 = fmaf(kA.x, pA, m0);
                m1 = fmaf(kA.y, pA, m1);
                m2 = fmaf(kB.x, pB, m2);
                m3 = fmaf(kB.y, pB, m3);
            }
        }
    }

    // ---- Register GEMV: 10 outputs, features [4p, 4p+4) ----
    float acc[10];
    #pragma unroll
    for (int k = 0; k < 10; k++) acc[k] = 0.f;
    if (act) {
        #pragma unroll
        for (int k = 0; k < 10; k++) {
            float4 w4 = __ldg((const float4*)(W + k * 784 + 4 * p));
            acc[k] = fmaf(m0, w4.x, fmaf(m1, w4.y, fmaf(m2, w4.z, m3 * w4.w)));
        }
    }

    // ---- Warp reduction (each warp holds one image only) ----
    #pragma unroll
    for (int k = 0; k < 10; k++) {
        float v = acc[k];
        #pragma unroll
        for (int d = 16; d > 0; d >>= 1)
            v += __shfl_xor_sync(0xffffffffu, v, d);
        acc[k] = v;
    }
    if (lane == 0) {
        #pragma unroll
        for (int k = 0; k < 10; k++) wpart[wid][k] = acc[k];
    }
    __syncthreads();

    // ---- Final logits + dual log_softmax (warp 0 only) ----
    if (t < 32) {
        if (t < 20) {
            int im = t / 10, k = t % 10;
            float v = bvec[k];
            #pragma unroll
            for (int w = 0; w < 7; w++) v += wpart[im * 7 + w][k];
            slog[im][k] = v;
        }
        __syncwarp();
        if (t < 2) {
            float mx = slog[t][0];
            #pragma unroll
            for (int k = 1; k < 10; k++) mx = fmaxf(mx, slog[t][k]);
            float se = 0.f;
            #pragma unroll
            for (int k = 0; k < 10; k++) se += __expf(slog[t][k] - mx);
            slse[t] = mx + __logf(se);
        }
        __syncwarp();
        if (t < 20) {
            int im = t / 10, k = t % 10;
            out[(size_t)(2 * b + im) * 10 + k] = slog[im][k] - slse[im];
        }
    }
}

// ---------------------------------------------------------------------------

extern "C" void kernel_launch(void* const* d_in, const int* in_sizes, int n_in,
                              void* d_out, int out_size)
{
    const float* x     = (const float*)d_in[0];   // [2048,1,56,56]
    const float* cw    = (const float*)d_in[1];   // [1,1,2,2]
    const float* theta = (const float*)d_in[2];   // [6]
    const float* W     = (const float*)d_in[3];   // [10,784]
    const float* bvec  = (const float*)d_in[4];   // [10]
    float* out = (float*)d_out;                   // [2048,10]

    int B = in_sizes[0] / 3136;                   // 2048

    fused_kernel<<<B / 2, 448>>>(x, cw, theta, W, bvec, out);
}